// round 2
// baseline (speedup 1.0000x reference)
#include <cuda_runtime.h>
#include <cuda_bf16.h>

#define Nw 32768
#define Tc 20
#define Ec 50
#define Hc 50
#define Vc 200

// Precomputed input-gate table: G[dir][v][4H] = emb[v] @ W_ih_d^T + b_ih_d + b_hh_d
__device__ float g_table[2 * Vc * 200];

__global__ void build_table_kernel(
    const float* __restrict__ emb,
    const float* __restrict__ Wih_f, const float* __restrict__ bih_f, const float* __restrict__ bhh_f,
    const float* __restrict__ Wih_b, const float* __restrict__ bih_b, const float* __restrict__ bhh_b)
{
    int v = blockIdx.x;        // char value 0..199
    int dir = blockIdx.y;      // 0 = forward, 1 = backward
    int j = threadIdx.x;       // gate index 0..199
    const float* Wih = dir ? Wih_b : Wih_f;
    const float* bih = dir ? bih_b : bih_f;
    const float* bhh = dir ? bhh_b : bhh_f;

    __shared__ float xs[64];
    if (j < Ec) xs[j] = (v == 0) ? 0.f : emb[v * Ec + j];  // padding_idx row zeroed
    __syncthreads();

    float a = bih[j] + bhh[j];
    const float* wr = Wih + j * Ec;
    #pragma unroll
    for (int e = 0; e < Ec; e++) a += xs[e] * wr[e];
    g_table[(dir * Vc + v) * 200 + j] = a;
}

__device__ __forceinline__ float sigm(float x) {
    float e = __expf(-x);
    return __fdividef(1.f, 1.f + e);
}
__device__ __forceinline__ float tanh_(float x) {
    x = fminf(fmaxf(x, -15.f), 15.f);
    float e = __expf(2.f * x);
    return __fdividef(e - 1.f, e + 1.f);
}

#define GROUPS_PER_BLOCK 4
#define NBLOCKS 148

__global__ __launch_bounds__(256, 1) void lstm_kernel(
    const int* __restrict__ chars, const int* __restrict__ lens,
    const float* __restrict__ Whh_f, const float* __restrict__ Whh_b,
    float* __restrict__ out)
{
    __shared__ __align__(16) float hbuf[GROUPS_PER_BLOCK][2][56];
    __shared__ int csm[GROUPS_PER_BLOCK][Tc];

    const int gid = threadIdx.x >> 6;       // group in block (0..3)
    const int m   = threadIdx.x & 63;       // lane in group; m<50 active
    const int barid = gid + 1;              // named barrier per group

    const int groups_total = gridDim.x * GROUPS_PER_BLOCK;
    const int gg = blockIdx.x * GROUPS_PER_BLOCK + gid;
    const int total_tasks = 2 * Nw;
    const int chunk = (total_tasks + groups_total - 1) / groups_total;
    int task = gg * chunk;
    const int tend = min(task + chunk, total_tasks);

    // W_hh rows for this thread's output index m, kept in registers.
    float Wi[50], Wf[50], Wg[50], Wo[50];

    while (task < tend) {
        const int dir = (task >= Nw) ? 1 : 0;
        const float* Whh = dir ? Whh_b : Whh_f;
        if (m < 50) {
            #pragma unroll
            for (int k = 0; k < 50; k++) Wi[k] = Whh[m * 50 + k];
            #pragma unroll
            for (int k = 0; k < 50; k++) Wf[k] = Whh[(50 + m) * 50 + k];
            #pragma unroll
            for (int k = 0; k < 50; k++) Wg[k] = Whh[(100 + m) * 50 + k];
            #pragma unroll
            for (int k = 0; k < 50; k++) Wo[k] = Whh[(150 + m) * 50 + k];
        }
        const int seg_end = dir ? tend : min(tend, Nw);
        const float* Gd = g_table + dir * Vc * 200;

        for (; task < seg_end; ++task) {
            const int w = task - dir * Nw;
            const int len = lens[w];

            // Stage chars + zero h buffers (protected by the barrier below)
            if (m < Tc) csm[gid][m] = chars[w * Tc + m];
            if (m < 56) { hbuf[gid][0][m] = 0.f; hbuf[gid][1][m] = 0.f; }
            asm volatile("bar.sync %0, 64;" :: "r"(barid) : "memory");

            float hlast = 0.f, cst = 0.f;
            int p = 0;
            float xi = 0.f, xf = 0.f, xG = 0.f, xo = 0.f;
            if (m < 50 && len > 0) {
                int c0 = csm[gid][dir ? (len - 1) : 0];
                const float* Gp = Gd + c0 * 200 + m;
                xi = Gp[0]; xf = Gp[50]; xG = Gp[100]; xo = Gp[150];
            }

            for (int s = 0; s < len; ++s) {
                if (m < 50) {
                    float gi = xi, gf = xf, gG = xG, go = xo;
                    // Prefetch next step's input gates while FMAs run
                    if (s + 1 < len) {
                        int t1 = dir ? (len - 2 - s) : (s + 1);
                        int c1 = csm[gid][t1];
                        const float* Gp = Gd + c1 * 200 + m;
                        xi = Gp[0]; xf = Gp[50]; xG = Gp[100]; xo = Gp[150];
                    }
                    const float* hb = hbuf[gid][p];
                    #pragma unroll
                    for (int kk = 0; kk < 12; kk++) {
                        float4 h4 = *reinterpret_cast<const float4*>(hb + 4 * kk);
                        gi += h4.x * Wi[4*kk+0]; gf += h4.x * Wf[4*kk+0];
                        gG += h4.x * Wg[4*kk+0]; go += h4.x * Wo[4*kk+0];
                        gi += h4.y * Wi[4*kk+1]; gf += h4.y * Wf[4*kk+1];
                        gG += h4.y * Wg[4*kk+1]; go += h4.y * Wo[4*kk+1];
                        gi += h4.z * Wi[4*kk+2]; gf += h4.z * Wf[4*kk+2];
                        gG += h4.z * Wg[4*kk+2]; go += h4.z * Wo[4*kk+2];
                        gi += h4.w * Wi[4*kk+3]; gf += h4.w * Wf[4*kk+3];
                        gG += h4.w * Wg[4*kk+3]; go += h4.w * Wo[4*kk+3];
                    }
                    float2 h2 = *reinterpret_cast<const float2*>(hb + 48);
                    gi += h2.x * Wi[48]; gf += h2.x * Wf[48];
                    gG += h2.x * Wg[48]; go += h2.x * Wo[48];
                    gi += h2.y * Wi[49]; gf += h2.y * Wf[49];
                    gG += h2.y * Wg[49]; go += h2.y * Wo[49];

                    float is = sigm(gi), fs = sigm(gf), os = sigm(go);
                    cst = fs * cst + is * tanh_(gG);
                    float hn = os * tanh_(cst);
                    hbuf[gid][p ^ 1][m] = hn;
                    hlast = hn;
                }
                p ^= 1;
                asm volatile("bar.sync %0, 64;" :: "r"(barid) : "memory");
            }

            if (m < 50) out[w * 100 + dir * 50 + m] = hlast;
        }
    }
}

extern "C" void kernel_launch(void* const* d_in, const int* in_sizes, int n_in,
                              void* d_out, int out_size) {
    const int*   chars = (const int*)d_in[0];
    const int*   lens  = (const int*)d_in[1];
    const float* emb   = (const float*)d_in[2];
    const float* Wih_f = (const float*)d_in[3];
    const float* Whh_f = (const float*)d_in[4];
    const float* bih_f = (const float*)d_in[5];
    const float* bhh_f = (const float*)d_in[6];
    const float* Wih_b = (const float*)d_in[7];
    const float* Whh_b = (const float*)d_in[8];
    const float* bih_b = (const float*)d_in[9];
    const float* bhh_b = (const float*)d_in[10];
    float* out = (float*)d_out;

    dim3 gt(Vc, 2);
    build_table_kernel<<<gt, 200>>>(emb, Wih_f, bih_f, bhh_f, Wih_b, bih_b, bhh_b);
    lstm_kernel<<<NBLOCKS, 256>>>(chars, lens, Whh_f, Whh_b, out);
}

// round 4
// speedup vs baseline: 1.0262x; 1.0262x over previous
#include <cuda_runtime.h>
#include <cuda_bf16.h>

#define Nw 32768
#define Tc 20
#define Ec 50
#define Hc 50
#define Vc 200

typedef unsigned long long u64;

// Precomputed input-gate table, layout [dir][v][m][4gates] so one LDG.128
// fetches all four gate pre-activations for output index m.
__device__ float g_table[2 * Vc * 200];

__global__ void build_table_kernel(
    const float* __restrict__ emb,
    const float* __restrict__ Wih_f, const float* __restrict__ bih_f, const float* __restrict__ bhh_f,
    const float* __restrict__ Wih_b, const float* __restrict__ bih_b, const float* __restrict__ bhh_b)
{
    int v = blockIdx.x;        // char value 0..199
    int dir = blockIdx.y;      // 0 = forward, 1 = backward
    int j = threadIdx.x;       // gate-major index 0..199: j = gate*50 + m
    const float* Wih = dir ? Wih_b : Wih_f;
    const float* bih = dir ? bih_b : bih_f;
    const float* bhh = dir ? bhh_b : bhh_f;

    __shared__ float xs[64];
    if (j < Ec) xs[j] = (v == 0) ? 0.f : emb[v * Ec + j];  // padding_idx row zeroed
    __syncthreads();

    float a = bih[j] + bhh[j];
    const float* wr = Wih + j * Ec;
    #pragma unroll
    for (int e = 0; e < Ec; e++) a += xs[e] * wr[e];

    int gate = j / 50, m = j % 50;
    g_table[(dir * Vc + v) * 200 + m * 4 + gate] = a;
}

__device__ __forceinline__ float sigm(float x) {
    float e = __expf(-x);
    return __fdividef(1.f, 1.f + e);
}
__device__ __forceinline__ float tanh_(float x) {
    x = fminf(fmaxf(x, -15.f), 15.f);
    float e = __expf(2.f * x);
    return __fdividef(e - 1.f, e + 1.f);
}

// Packed dual-FMA: d.lane += a.lane * b.lane (two fp32 per instruction).
__device__ __forceinline__ void fma2(u64& d, u64 a, u64 b) {
    asm("fma.rn.f32x2 %0, %1, %2, %0;" : "+l"(d) : "l"(a), "l"(b));
}
__device__ __forceinline__ float hsum2(u64 v) {
    float lo, hi;
    asm("mov.b64 {%0, %1}, %2;" : "=f"(lo), "=f"(hi) : "l"(v));
    return lo + hi;
}
__device__ __forceinline__ u64 pack_lo(float x) {
    return (u64)__float_as_uint(x);   // low lane = x, high lane = 0
}

#define GROUPS_PER_BLOCK 4
#define NBLOCKS 148

__global__ __launch_bounds__(256, 1) void lstm_kernel(
    const int* __restrict__ chars, const int* __restrict__ lens,
    const float* __restrict__ Whh_f, const float* __restrict__ Whh_b,
    float* __restrict__ out)
{
    __shared__ __align__(16) float hbuf[GROUPS_PER_BLOCK][2][56];
    __shared__ int csm[GROUPS_PER_BLOCK][Tc];

    const int gid = threadIdx.x >> 6;       // group in block (0..3)
    const int m   = threadIdx.x & 63;       // lane in group; m<50 active
    const int barid = gid + 1;              // named barrier per group

    const int groups_total = gridDim.x * GROUPS_PER_BLOCK;
    const int gg = blockIdx.x * GROUPS_PER_BLOCK + gid;
    const int total_tasks = 2 * Nw;
    const int chunk = (total_tasks + groups_total - 1) / groups_total;
    int task = gg * chunk;
    const int tend = min(task + chunk, total_tasks);

    // W_hh rows for this thread's output m, packed as (k, k+1) fp32 pairs.
    u64 Wi2[25], Wf2[25], Wg2[25], Wo2[25];

    while (task < tend) {
        const int dir = (task >= Nw) ? 1 : 0;
        const float* Whh = dir ? Whh_b : Whh_f;
        if (m < 50) {
            const u64* ri = (const u64*)(Whh + m * 50);          // 8B-aligned: 200m bytes
            const u64* rf = (const u64*)(Whh + (50 + m) * 50);
            const u64* rg = (const u64*)(Whh + (100 + m) * 50);
            const u64* ro = (const u64*)(Whh + (150 + m) * 50);
            #pragma unroll
            for (int k = 0; k < 25; k++) Wi2[k] = ri[k];
            #pragma unroll
            for (int k = 0; k < 25; k++) Wf2[k] = rf[k];
            #pragma unroll
            for (int k = 0; k < 25; k++) Wg2[k] = rg[k];
            #pragma unroll
            for (int k = 0; k < 25; k++) Wo2[k] = ro[k];
        }
        const int seg_end = dir ? tend : min(tend, Nw);
        const float* Gd = g_table + dir * Vc * 200;

        for (; task < seg_end; ++task) {
            const int w = task - dir * Nw;
            const int len = lens[w];

            // Stage chars + zero h buffers (protected by the barrier below)
            if (m < Tc) csm[gid][m] = chars[w * Tc + m];
            if (m < 56) { hbuf[gid][0][m] = 0.f; hbuf[gid][1][m] = 0.f; }
            asm volatile("bar.sync %0, 64;" :: "r"(barid) : "memory");

            float hlast = 0.f, cst = 0.f;
            int p = 0;
            float4 xg = make_float4(0.f, 0.f, 0.f, 0.f);
            if (m < 50 && len > 0) {
                int c0 = csm[gid][dir ? (len - 1) : 0];
                xg = *(const float4*)(Gd + c0 * 200 + m * 4);
            }

            for (int s = 0; s < len; ++s) {
                if (m < 50) {
                    u64 ai = pack_lo(xg.x), af = pack_lo(xg.y);
                    u64 ag = pack_lo(xg.z), ao = pack_lo(xg.w);
                    // Prefetch next step's input gates while FMAs run
                    if (s + 1 < len) {
                        int t1 = dir ? (len - 2 - s) : (s + 1);
                        int c1 = csm[gid][t1];
                        xg = *(const float4*)(Gd + c1 * 200 + m * 4);
                    }
                    const float* hb = hbuf[gid][p];
                    #pragma unroll
                    for (int kk = 0; kk < 12; kk++) {
                        ulonglong2 hv = *(const ulonglong2*)(hb + 4 * kk); // (h2k,h2k+1),(h2k+2,h2k+3)
                        fma2(ai, hv.x, Wi2[2*kk+0]);
                        fma2(af, hv.x, Wf2[2*kk+0]);
                        fma2(ag, hv.x, Wg2[2*kk+0]);
                        fma2(ao, hv.x, Wo2[2*kk+0]);
                        fma2(ai, hv.y, Wi2[2*kk+1]);
                        fma2(af, hv.y, Wf2[2*kk+1]);
                        fma2(ag, hv.y, Wg2[2*kk+1]);
                        fma2(ao, hv.y, Wo2[2*kk+1]);
                    }
                    u64 ht = *(const u64*)(hb + 48);                       // (h48,h49)
                    fma2(ai, ht, Wi2[24]);
                    fma2(af, ht, Wf2[24]);
                    fma2(ag, ht, Wg2[24]);
                    fma2(ao, ht, Wo2[24]);

                    float gi = hsum2(ai), gf = hsum2(af);
                    float gG = hsum2(ag), go = hsum2(ao);

                    float is = sigm(gi), fs = sigm(gf), os = sigm(go);
                    cst = fs * cst + is * tanh_(gG);
                    float hn = os * tanh_(cst);
                    hbuf[gid][p ^ 1][m] = hn;
                    hlast = hn;
                }
                p ^= 1;
                asm volatile("bar.sync %0, 64;" :: "r"(barid) : "memory");
            }

            if (m < 50) out[w * 100 + dir * 50 + m] = hlast;
        }
    }
}

extern "C" void kernel_launch(void* const* d_in, const int* in_sizes, int n_in,
                              void* d_out, int out_size) {
    const int*   chars = (const int*)d_in[0];
    const int*   lens  = (const int*)d_in[1];
    const float* emb   = (const float*)d_in[2];
    const float* Wih_f = (const float*)d_in[3];
    const float* Whh_f = (const float*)d_in[4];
    const float* bih_f = (const float*)d_in[5];
    const float* bhh_f = (const float*)d_in[6];
    const float* Wih_b = (const float*)d_in[7];
    const float* Whh_b = (const float*)d_in[8];
    const float* bih_b = (const float*)d_in[9];
    const float* bhh_b = (const float*)d_in[10];
    float* out = (float*)d_out;

    dim3 gt(Vc, 2);
    build_table_kernel<<<gt, 200>>>(emb, Wih_f, bih_f, bhh_f, Wih_b, bih_b, bhh_b);
    lstm_kernel<<<NBLOCKS, 256>>>(chars, lens, Whh_f, Whh_b, out);
}